// round 2
// baseline (speedup 1.0000x reference)
#include <cuda_runtime.h>
#include <cstdint>

#define SEQ_LEN 131072
#define NT      128
#define NCTA    148
#define THREADS 256
#define CHUNK   888
#define WARM    32

// per-CTA partial results (rewritten every launch -> deterministic, graph-safe)
__device__ double g_gold[NCTA];
__device__ double g_tot[NCTA];

// ---------------- packed f32x2 helpers (Blackwell) ----------------
__device__ __forceinline__ unsigned long long pack2f(float lo, float hi) {
    unsigned long long r;
    asm("mov.b64 %0, {%1, %2};" : "=l"(r) : "f"(lo), "f"(hi));
    return r;
}
__device__ __forceinline__ void fma2(unsigned long long &acc, unsigned long long a,
                                     unsigned long long b) {
    asm("fma.rn.f32x2 %0, %1, %2, %0;" : "+l"(acc) : "l"(a), "l"(b));
}
__device__ __forceinline__ unsigned long long add2(unsigned long long a,
                                                   unsigned long long b) {
    unsigned long long r;
    asm("add.rn.f32x2 %0, %1, %2;" : "=l"(r) : "l"(a), "l"(b));
    return r;
}
__device__ __forceinline__ float2 unpack2f(unsigned long long v) {
    float2 r;
    asm("mov.b64 {%0, %1}, %2;" : "=f"(r.x), "=f"(r.y) : "l"(v));
    return r;
}

// ---------------- emission/w2w tile prefetch (8 steps = 4KB + 32B) ----------------
__device__ __forceinline__ void tile_copy(const float* __restrict__ em,
                                          const int* __restrict__ w2w,
                                          int tbase, float* embuf, int* w2wbuf, int tid)
{
    int r   = tid >> 5;          // row 0..7
    int col = (tid & 31) << 2;   // 4-float chunk
    int row = tbase + r;
    if (row > SEQ_LEN - 1) row = SEQ_LEN - 1;       // clamp: content unused past t_hi
    const float* src = em + (size_t)row * NT + col;
    unsigned sdst = (unsigned)__cvta_generic_to_shared(embuf + r * NT + col);
    asm volatile("cp.async.cg.shared.global [%0], [%1], 16;" :: "r"(sdst), "l"(src));
    if (tid < 2) {
        int base = tbase + tid * 4;
        int nb = (SEQ_LEN - base) * 4;              // zero-fill OOB tail (keeps alignment!)
        if (nb < 0) nb = 0;
        if (nb > 16) nb = 16;
        int cbase = base; if (cbase > SEQ_LEN - 4) cbase = SEQ_LEN - 4;
        const int* s2 = w2w + cbase;
        unsigned d2 = (unsigned)__cvta_generic_to_shared(w2wbuf + tid * 4);
        asm volatile("cp.async.cg.shared.global [%0], [%1], 16, %2;"
                     :: "r"(d2), "l"(s2), "r"(nb));
    }
}

// ---------------- main kernel: gold reduce + chunked forward scan ----------------
__global__ void __launch_bounds__(THREADS, 1)
crf_main(const float* __restrict__ em, const int* __restrict__ tags,
         const int* __restrict__ w2w, const float* __restrict__ trans_g,
         const float* __restrict__ trans_u2s, const float* __restrict__ trans_s2u)
{
    __shared__ __align__(16) float vbuf[2][NT];
    __shared__ __align__(16) float embuf[2][8 * NT];
    __shared__ __align__(16) int   w2wbuf[2][8];
    __shared__ float partials[4];
    __shared__ float fpart[4];
    __shared__ double sgold[8];

    const int tid  = threadIdx.x;
    const int cta  = blockIdx.x;
    const int lane = tid & 31;
    const int warp = tid >> 5;
    const int team = tid >> 7;     // team 0 owns exp(trans_u2s) (w2w==0), team 1 exp(trans_s2u)
    const int j    = tid & 127;    // output column this thread owns

    // ======== phase 1: gold path score (grid-stride, deterministic reduce) ========
    double gacc = 0.0;
    for (int t = cta * THREADS + tid; t < SEQ_LEN; t += NCTA * THREADS) {
        int tcur = tags[t];
        gacc += (double)em[(size_t)t * NT + tcur];
        if (t >= 1) {
            int tprev = tags[t - 1];
            const float* tm = (w2w[t] == 0) ? trans_u2s : trans_s2u;
            gacc += (double)tm[tprev * NT + tcur];
        }
    }
    #pragma unroll
    for (int o = 16; o; o >>= 1) gacc += __shfl_down_sync(0xffffffffu, gacc, o);
    if (lane == 0) sgold[warp] = gacc;
    __syncthreads();
    if (tid == 0) {
        double s = 0.0;
        #pragma unroll
        for (int wv = 0; wv < 8; wv++) s += sgold[wv];
        g_gold[cta] = s;
    }

    // ======== phase 2: K column -> registers, packed as f32x2 pairs over i ========
    const float* km = (team == 0) ? trans_u2s : trans_s2u;
    unsigned long long k2[64];
    #pragma unroll
    for (int m = 0; m < 64; m++) {
        float a = __expf(km[(2 * m) * NT + j]);
        float b = __expf(km[(2 * m + 1) * NT + j]);
        k2[m] = pack2f(a, b);
    }

    // ======== phase 3: chunked forward scan ========
    const int t_lo = 1 + cta * CHUNK;
    const int t_hi = min(SEQ_LEN, t_lo + CHUNK);
    const int t0   = (cta == 0) ? 1 : (t_lo - WARM);   // first processed step
    const int nsteps = t_hi - t0;
    const int ntiles = (nsteps + 7) >> 3;
    const int count_from = (cta == 0) ? 1 : (WARM / 8 + 1);  // first tile whose entry-renorm counts

    if (tid < NT) vbuf[0][tid] = (cta == 0) ? __expf(em[tid]) : 1.0f;

    tile_copy(em, w2w, t0,     embuf[0], w2wbuf[0], tid);
    asm volatile("cp.async.commit_group;" ::: "memory");
    tile_copy(em, w2w, t0 + 8, embuf[1], w2wbuf[1], tid);
    asm volatile("cp.async.commit_group;" ::: "memory");

    double lam = 0.0;      // replicated across all threads (identical arithmetic)
    float  inv = 1.0f;
    int    cur = 0;

    for (int k = 0; k < ntiles; k++) {
        asm volatile("cp.async.wait_group 1;" ::: "memory");
        __syncthreads();
        const int buf   = k & 1;
        const int tbase = t0 + 8 * k;

        // lazy renorm bookkeeping from previous tile's reduction
        if (k > 0) {
            float sval = partials[0] + partials[1] + partials[2] + partials[3];
            if (k >= count_from) lam += (double)logf(sval);
            inv = __fdividef(1.0f, sval);
        }

        #pragma unroll 1
        for (int s = 0; s < 8; s++) {
            const int t = tbase + s;
            if (t >= t_hi) break;                 // uniform across CTA
            const int wv = w2wbuf[buf][s];
            if (team == wv) {
                const ulonglong2* vb = (const ulonglong2*)&vbuf[cur][0];
                unsigned long long acc[8];
                #pragma unroll
                for (int a = 0; a < 8; a++) acc[a] = 0ull;
                #pragma unroll
                for (int m = 0; m < 32; m++) {    // 32x LDS.128 broadcast + 64x FFMA2
                    ulonglong2 q = vb[m];
                    fma2(acc[(2 * m) & 7],     q.x, k2[2 * m]);
                    fma2(acc[(2 * m + 1) & 7], q.y, k2[2 * m + 1]);
                }
                unsigned long long r0 = add2(add2(acc[0], acc[1]), add2(acc[2], acc[3]));
                unsigned long long r1 = add2(add2(acc[4], acc[5]), add2(acc[6], acc[7]));
                float2 f = unpack2f(add2(r0, r1));
                float ssum = f.x + f.y;
                float e = __expf(embuf[buf][s * NT + j]);
                float unew = e * ssum;
                if (s == 0) unew *= inv;          // apply pending renorm scale
                vbuf[cur ^ 1][j] = unew;
                if (s == 7) {                     // tile-end norm reduction
                    float r = unew;
                    #pragma unroll
                    for (int o = 16; o; o >>= 1) r += __shfl_xor_sync(0xffffffffu, r, o);
                    if (lane == 0) partials[warp & 3] = r;
                }
            }
            __syncthreads();
            cur ^= 1;
        }

        // prefetch tile k+2 into the buffer tile k just vacated
        tile_copy(em, w2w, t0 + 8 * (k + 2), embuf[buf], w2wbuf[buf], tid);
        asm volatile("cp.async.commit_group;" ::: "memory");
    }

    // final norm of the chunk's last state
    if (tid < NT) {
        float r = vbuf[cur][tid];
        #pragma unroll
        for (int o = 16; o; o >>= 1) r += __shfl_xor_sync(0xffffffffu, r, o);
        if (lane == 0) fpart[warp] = r;
    }
    __syncthreads();
    if (tid == 0) {
        float sfin = fpart[0] + fpart[1] + fpart[2] + fpart[3];
        g_tot[cta] = lam + (double)logf(sfin);
    }
}

// ---------------- finalize: deterministic sum of per-CTA partials ----------------
__global__ void crf_finalize(float* out) {
    int lane = threadIdx.x;
    double g = 0.0, t = 0.0;
    for (int i = lane; i < NCTA; i += 32) { g += g_gold[i]; t += g_tot[i]; }
    #pragma unroll
    for (int o = 16; o; o >>= 1) {
        g += __shfl_down_sync(0xffffffffu, g, o);
        t += __shfl_down_sync(0xffffffffu, t, o);
    }
    if (lane == 0) { out[0] = (float)g; out[1] = (float)t; }
}

extern "C" void kernel_launch(void* const* d_in, const int* in_sizes, int n_in,
                              void* d_out, int out_size) {
    const float* em   = (const float*)d_in[0];
    const int*   tags = (const int*)d_in[1];
    const int*   w2w  = (const int*)d_in[2];
    const float* tg   = (const float*)d_in[3];
    const float* tu2s = (const float*)d_in[4];
    const float* ts2u = (const float*)d_in[5];
    crf_main<<<NCTA, THREADS>>>(em, tags, w2w, tg, tu2s, ts2u);
    crf_finalize<<<1, 32>>>((float*)d_out);
}

// round 5
// speedup vs baseline: 1.6906x; 1.6906x over previous
#include <cuda_runtime.h>
#include <cuda_bf16.h>
#include <cstdint>

#define SEQ_LEN 131072
#define NT      128
#define NCTA    293     /* = ceil((SEQ_LEN-1)/CHUNK): every CTA owns a real chunk */
#define THREADS 128
#define CHUNK   448
#define WARM    16

// per-CTA partial results (rewritten every launch -> deterministic, graph-safe)
__device__ double g_gold[NCTA];
__device__ double g_tot[NCTA];

__device__ __forceinline__ void cp16(void* dst_smem, const void* src) {
    unsigned d = (unsigned)__cvta_generic_to_shared(dst_smem);
    asm volatile("cp.async.cg.shared.global [%0], [%1], 16;" :: "r"(d), "l"(src));
}

// ---- emission/w2w tile prefetch: 8 steps = 4KB em + 32B w2w ----
__device__ __forceinline__ void tile_copy(const float* __restrict__ em,
                                          const int* __restrict__ w2w,
                                          int tbase, float* embuf, int* w2wbuf, int tid)
{
    int r = tid >> 4;            // row 0..7
    int c = tid & 15;            // 16B-chunk index
    int row = tbase + r;
    if (row > SEQ_LEN - 1) row = SEQ_LEN - 1;      // clamp: content unused past t_hi
    const float* src = em + (size_t)row * NT;
    cp16(embuf + r * NT + c * 4,       src + c * 4);
    cp16(embuf + r * NT + 64 + c * 4,  src + 64 + c * 4);
    if (tid < 2) {
        int base = tbase + tid * 4;
        int nb = (SEQ_LEN - base) * 4;             // zero-fill OOB tail
        if (nb < 0) nb = 0;
        if (nb > 16) nb = 16;
        int cbase = base; if (cbase > SEQ_LEN - 4) cbase = SEQ_LEN - 4;
        unsigned d2 = (unsigned)__cvta_generic_to_shared(w2wbuf + tid * 4);
        asm volatile("cp.async.cg.shared.global [%0], [%1], 16, %2;"
                     :: "r"(d2), "l"(w2w + cbase), "r"(nb));
    }
}

// ---- one CRF step: 128-length dot in bf16x2 (64 HFMA2), returns fp32 sum ----
__device__ __forceinline__ float dot_step(const __nv_bfloat162 (&k)[64],
                                          const __nv_bfloat162* __restrict__ vsrc)
{
    const uint4* vb = (const uint4*)vsrc;
    __nv_bfloat162 z = __float2bfloat162_rn(0.0f);
    __nv_bfloat162 acc[8] = {z, z, z, z, z, z, z, z};
    #pragma unroll
    for (int q = 0; q < 16; q++) {
        uint4 u = vb[q];
        acc[(4 * q + 0) & 7] = __hfma2(*(const __nv_bfloat162*)&u.x, k[4 * q + 0], acc[(4 * q + 0) & 7]);
        acc[(4 * q + 1) & 7] = __hfma2(*(const __nv_bfloat162*)&u.y, k[4 * q + 1], acc[(4 * q + 1) & 7]);
        acc[(4 * q + 2) & 7] = __hfma2(*(const __nv_bfloat162*)&u.z, k[4 * q + 2], acc[(4 * q + 2) & 7]);
        acc[(4 * q + 3) & 7] = __hfma2(*(const __nv_bfloat162*)&u.w, k[4 * q + 3], acc[(4 * q + 3) & 7]);
    }
    __nv_bfloat162 b0 = __hadd2(acc[0], acc[1]);
    __nv_bfloat162 b1 = __hadd2(acc[2], acc[3]);
    __nv_bfloat162 b2 = __hadd2(acc[4], acc[5]);
    __nv_bfloat162 b3 = __hadd2(acc[6], acc[7]);
    __nv_bfloat162 c0 = __hadd2(b0, b1);
    __nv_bfloat162 c1 = __hadd2(b2, b3);
    __nv_bfloat162 d  = __hadd2(c0, c1);
    return __low2float(d) + __high2float(d);
}

// ---- main kernel: gold reduce + chunked warm-started forward scan ----
__global__ void __launch_bounds__(THREADS, 2)
crf_main(const float* __restrict__ em, const int* __restrict__ tags,
         const int* __restrict__ w2w, const float* __restrict__ trans_g,
         const float* __restrict__ trans_u2s, const float* __restrict__ trans_s2u)
{
    __shared__ __align__(16) __nv_bfloat16 vbuf[2][NT];
    __shared__ __align__(16) float embuf[2][8 * NT];
    __shared__ __align__(16) int   w2wbuf[2][8];
    __shared__ float partials[4];
    __shared__ float fpart[4];
    __shared__ double sgold[4];

    const int tid  = threadIdx.x;
    const int cta  = blockIdx.x;
    const int lane = tid & 31;
    const int warp = tid >> 5;
    const int j    = tid;          // output column this thread owns

    // ======== phase 1: gold path score (grid-stride, fp64, deterministic) ========
    double gacc = 0.0;
    for (int t = cta * THREADS + tid; t < SEQ_LEN; t += NCTA * THREADS) {
        int tcur = tags[t];
        gacc += (double)em[(size_t)t * NT + tcur];
        if (t >= 1) {
            int tprev = tags[t - 1];
            const float* tm = (w2w[t] == 0) ? trans_u2s : trans_s2u;
            gacc += (double)tm[tprev * NT + tcur];
        }
    }
    #pragma unroll
    for (int o = 16; o; o >>= 1) gacc += __shfl_down_sync(0xffffffffu, gacc, o);
    if (lane == 0) sgold[warp] = gacc;
    __syncthreads();
    if (tid == 0) g_gold[cta] = sgold[0] + sgold[1] + sgold[2] + sgold[3];

    // ======== phase 2: both K matrices' column j -> bf16x2 registers ========
    __nv_bfloat162 ka[64], kb[64];
    #pragma unroll
    for (int m = 0; m < 64; m++) {
        ka[m] = __floats2bfloat162_rn(__expf(trans_u2s[(2 * m) * NT + j]),
                                      __expf(trans_u2s[(2 * m + 1) * NT + j]));
        kb[m] = __floats2bfloat162_rn(__expf(trans_s2u[(2 * m) * NT + j]),
                                      __expf(trans_s2u[(2 * m + 1) * NT + j]));
    }

    // ======== phase 3: chunked forward scan with warm-start ========
    const int t_lo = 1 + cta * CHUNK;                 // always < SEQ_LEN (NCTA exact)
    const int t_hi = min(SEQ_LEN, t_lo + CHUNK);
    const int t0   = (cta == 0) ? 1 : (t_lo - WARM);
    const int ntiles = (t_hi - t0 + 7) >> 3;
    const int count_from = (cta == 0) ? 1 : (WARM / 8 + 1);

    vbuf[0][j] = (cta == 0) ? __float2bfloat16(__expf(em[j])) : __float2bfloat16(1.0f);

    tile_copy(em, w2w, t0,     embuf[0], w2wbuf[0], tid);
    asm volatile("cp.async.commit_group;" ::: "memory");
    tile_copy(em, w2w, t0 + 8, embuf[1], w2wbuf[1], tid);
    asm volatile("cp.async.commit_group;" ::: "memory");

    double lam = 0.0;     // replicated across threads (identical arithmetic)
    float  inv = 1.0f;
    int    cur = 0;

    for (int k = 0; k < ntiles; k++) {
        asm volatile("cp.async.wait_group 1;" ::: "memory");
        __syncthreads();
        const int buf   = k & 1;
        const int tbase = t0 + 8 * k;

        if (k > 0) {   // lazy renorm bookkeeping from previous tile's reduction
            float sval = partials[0] + partials[1] + partials[2] + partials[3];
            if (k >= count_from) lam += (double)logf(sval);
            inv = __fdividef(1.0f, sval);
        }

        #pragma unroll
        for (int s = 0; s < 8; s++) {
            if (tbase + s >= t_hi) break;              // uniform across CTA
            const __nv_bfloat162* vsrc = (const __nv_bfloat162*)&vbuf[cur][0];
            float ssum;
            if (w2wbuf[buf][s] == 0) ssum = dot_step(ka, vsrc);
            else                     ssum = dot_step(kb, vsrc);
            float e = __expf(embuf[buf][s * NT + j]);
            float unew = e * ssum;
            if (s == 0) unew *= inv;                   // apply pending renorm scale
            vbuf[cur ^ 1][j] = __float2bfloat16(unew);
            if (s == 7) {                              // tile-end norm reduction (fp32)
                float r = unew;
                #pragma unroll
                for (int o = 16; o; o >>= 1) r += __shfl_xor_sync(0xffffffffu, r, o);
                if (lane == 0) partials[warp] = r;
            }
            __syncthreads();
            cur ^= 1;
        }

        // prefetch tile k+2 into the buffer tile k just vacated
        tile_copy(em, w2w, t0 + 8 * (k + 2), embuf[buf], w2wbuf[buf], tid);
        asm volatile("cp.async.commit_group;" ::: "memory");
    }

    // final norm of the chunk's last state
    {
        float r = __bfloat162float(vbuf[cur][j]);
        #pragma unroll
        for (int o = 16; o; o >>= 1) r += __shfl_xor_sync(0xffffffffu, r, o);
        if (lane == 0) fpart[warp] = r;
    }
    __syncthreads();
    if (tid == 0) {
        float sfin = fpart[0] + fpart[1] + fpart[2] + fpart[3];
        g_tot[cta] = lam + (double)logf(sfin);
    }
}

// ---- finalize: deterministic sum of per-CTA partials ----
__global__ void crf_finalize(float* out) {
    int lane = threadIdx.x;
    double g = 0.0, t = 0.0;
    for (int i = lane; i < NCTA; i += 32) { g += g_gold[i]; t += g_tot[i]; }
    #pragma unroll
    for (int o = 16; o; o >>= 1) {
        g += __shfl_down_sync(0xffffffffu, g, o);
        t += __shfl_down_sync(0xffffffffu, t, o);
    }
    if (lane == 0) { out[0] = (float)g; out[1] = (float)t; }
}

extern "C" void kernel_launch(void* const* d_in, const int* in_sizes, int n_in,
                              void* d_out, int out_size) {
    const float* em   = (const float*)d_in[0];
    const int*   tags = (const int*)d_in[1];
    const int*   w2w  = (const int*)d_in[2];
    const float* tg   = (const float*)d_in[3];
    const float* tu2s = (const float*)d_in[4];
    const float* ts2u = (const float*)d_in[5];
    crf_main<<<NCTA, THREADS>>>(em, tags, w2w, tg, tu2s, ts2u);
    crf_finalize<<<1, 32>>>((float*)d_out);
}